// round 15
// baseline (speedup 1.0000x reference)
#include <cuda_runtime.h>
#include <cuda_fp16.h>
#include <cstdint>

#define N_NODES 50000
#define N_EDGES 500000
#define NT_EDGE ((N_EDGES + 127) / 128)   // 3907
#define NT_NODE ((N_NODES + 127) / 128)   // 391

#define FB_ZERO  6250
#define FB_PREP  163     // 8192 We-msg + 32768 node imgs + 640 Ctab, /256
#define FB_TOTAL (FB_ZERO + FB_PREP)

// ---------------- global scratch ----------------
__device__ uint32_t g_qh[(size_t)N_NODES * 64];
__device__ uint32_t g_kh[(size_t)N_NODES * 64];
__device__ uint32_t g_vh[(size_t)N_NODES * 64];
__device__ uint32_t g_acch[(size_t)N_NODES * 64];   // fp16x2 accumulator
__device__ float g_asum[(size_t)N_NODES * 2];
__device__ int   g_is64;
__device__ uint32_t g_imgWe_h[128 * 64];            // msg part of We, permuted N, K=128
__device__ uint32_t g_imgW_h[4][128 * 64], g_imgW_l[4][128 * 64];
__device__ float g_Ctab[5 * 128];                   // time-encoding Taylor tables (logical cols)

// fragment->contiguous column permutation (within each 64-col block)
__device__ __forceinline__ int permN(int n) {
    int p = n & 63;
    return (n & 64) + (((p & 7) >> 1) << 4) + ((p >> 3) << 1) + (p & 1);
}

// ---------------- helpers ----------------
__device__ __forceinline__ uint32_t s2u(const void* p) {
    uint32_t r;
    asm("{ .reg .u64 t; cvta.to.shared.u64 t, %1; cvt.u32.u64 %0, t; }" : "=r"(r) : "l"(p));
    return r;
}

__device__ __forceinline__ void ldsm4(uint32_t* r, uint32_t addr) {
    asm volatile("ldmatrix.sync.aligned.m8n8.x4.shared.b16 {%0,%1,%2,%3}, [%4];"
                 : "=r"(r[0]), "=r"(r[1]), "=r"(r[2]), "=r"(r[3]) : "r"(addr));
}

__device__ __forceinline__ void mma16816(float* d, const uint32_t* a, uint32_t b0, uint32_t b1) {
    asm volatile("mma.sync.aligned.m16n8k16.row.col.f32.f16.f16.f32 "
                 "{%0,%1,%2,%3}, {%4,%5,%6,%7}, {%8,%9}, {%0,%1,%2,%3};"
                 : "+f"(d[0]), "+f"(d[1]), "+f"(d[2]), "+f"(d[3])
                 : "r"(a[0]), "r"(a[1]), "r"(a[2]), "r"(a[3]), "r"(b0), "r"(b1));
}

__device__ __forceinline__ uint32_t packh2(float a, float b) {
    __half2 h = __floats2half2_rn(a, b);
    return *reinterpret_cast<uint32_t*>(&h);
}

__device__ __forceinline__ float2 unpackh2(uint32_t u) {
    return __half22float2(*reinterpret_cast<__half2*>(&u));
}

__device__ __forceinline__ void splith(float a, float b, uint32_t& hi, uint32_t& lo) {
    __half2 h = __floats2half2_rn(a, b);
    float ra = a - __low2float(h);
    float rb = b - __high2float(h);
    __half2 l = __floats2half2_rn(ra, rb);
    hi = *reinterpret_cast<uint32_t*>(&h);
    lo = *reinterpret_cast<uint32_t*>(&l);
}

__device__ __forceinline__ void ldg_ef8(const float* p, float* v) {
    uint32_t r0, r1, r2, r3, r4, r5, r6, r7;
    asm("ld.global.L2::evict_first.v8.b32 {%0,%1,%2,%3,%4,%5,%6,%7}, [%8];"
        : "=r"(r0), "=r"(r1), "=r"(r2), "=r"(r3),
          "=r"(r4), "=r"(r5), "=r"(r6), "=r"(r7) : "l"(p));
    v[0] = __uint_as_float(r0); v[1] = __uint_as_float(r1);
    v[2] = __uint_as_float(r2); v[3] = __uint_as_float(r3);
    v[4] = __uint_as_float(r4); v[5] = __uint_as_float(r5);
    v[6] = __uint_as_float(r6); v[7] = __uint_as_float(r7);
}

// ---------------- detect ----------------
__global__ void k_detect(const int* __restrict__ words)
{
    __shared__ int nz;
    if (threadIdx.x == 0) nz = 0;
    __syncthreads();
    int local = 0;
    for (int idx = threadIdx.x; idx < 4096; idx += blockDim.x)
        if (words[2 * idx + 1] != 0) local = 1;
    if (local) atomicOr(&nz, 1);
    __syncthreads();
    if (threadIdx.x == 0) g_is64 = (nz == 0) ? 1 : 0;
}

// ---------------- fused zero + prep ----------------
__global__ void k_fused(const float* __restrict__ We,
                        const float* __restrict__ Wq, const float* __restrict__ Wk,
                        const float* __restrict__ Wv, const float* __restrict__ Ws,
                        const float* __restrict__ tw, const float* __restrict__ tb)
{
    int b = blockIdx.x;
    if (b < FB_ZERO) {
        int i = b * 256 + threadIdx.x;
        if (i < N_NODES * 2) g_asum[i] = 0.f;
        if (i < N_NODES * 16) ((uint4*)g_acch)[i] = make_uint4(0u, 0u, 0u, 0u);
        return;
    }
    b -= FB_ZERO;
    {
        int idx = b * 256 + threadIdx.x;
        if (idx < 8192) {
            // msg part of We (rows 64..191), permuted N
            int n = idx >> 6, p = idx & 63;
            int ns = permN(n);
            float a  = We[(64 + 2 * p) * 128 + ns];
            float bb = We[(64 + 2 * p + 1) * 128 + ns];
            g_imgWe_h[idx] = packh2(a, bb);
        } else if (idx < 40960) {
            int r = idx - 8192;
            int mat = r >> 13;
            int w_  = r & 8191;
            int n = w_ >> 6, p = w_ & 63;
            int ns = permN(n);
            const float* W = (mat == 0) ? Wq : (mat == 1) ? Wk : (mat == 2) ? Wv : Ws;
            float a = W[(2 * p) * 128 + ns];
            float bb = W[(2 * p + 1) * 128 + ns];
            uint32_t h, l; splith(a, bb, h, l);
            g_imgW_h[mat][w_] = h; g_imgW_l[mat][w_] = l;
        } else if (idx < 41600) {
            // Taylor tables: C_k[c] = sum_j (w_j^k/k!) * cos^{(k)}(b_j) * We[j, c]
            int c640 = idx - 40960;
            int k = c640 >> 7;
            int c = c640 & 127;
            float acc = 0.f;
            for (int j = 0; j < 64; ++j) {
                float w = tw[j], bj = tb[j];
                float pk = 1.f;
                for (int q = 1; q <= k; ++q) pk *= w / (float)q;
                float tr;
                switch (k & 3) {
                    case 0: tr =  __cosf(bj); break;
                    case 1: tr = -__sinf(bj); break;
                    case 2: tr = -__cosf(bj); break;
                    default: tr =  __sinf(bj); break;
                }
                acc += pk * tr * We[j * 128 + c];
            }
            g_Ctab[k * 128 + c] = acc;
        }
    }
}

// ---------------- node GEMM: fp16 2-pass (B compensated), all 4 matrices ----------------
#define KN_SA 68
#define KN_SMEM (26112 * 4)

__global__ void __launch_bounds__(256, 2)
k_node_tc(const float* __restrict__ x,
          const float* __restrict__ bq, const float* __restrict__ bk,
          const float* __restrict__ bv, const float* __restrict__ bs,
          float* __restrict__ out)
{
    extern __shared__ uint32_t sm4[];
    const uint32_t sb = s2u(sm4);
    const int tid = threadIdx.x;
    const int wid = tid >> 5;
    const int lane = tid & 31;
    const int base = blockIdx.x * 128;

    uint32_t* AH = sm4;
    uint32_t* BH = sm4 + 8704;
    uint32_t* BL = sm4 + 17408;

    for (int idx = tid; idx < 128 * 16; idx += 256) {
        int i = idx >> 4, p4 = idx & 15;
        int node = base + i;
        float v[8] = {0.f, 0.f, 0.f, 0.f, 0.f, 0.f, 0.f, 0.f};
        if (node < N_NODES) ldg_ef8(x + (size_t)node * 128 + p4 * 8, v);
#pragma unroll
        for (int j = 0; j < 4; ++j)
            AH[i * KN_SA + p4 * 4 + j] = packh2(v[2 * j], v[2 * j + 1]);
    }

    const int wm = wid & 3;
    const int wn = wid >> 2;
    const int lrow = lane & 15;
    const int lk   = (lane >> 4) * 8;
    const int l2   = lane & 3;
    const int lr   = lane >> 2;

    for (int mat = 0; mat < 4; ++mat) {
        {
            const uint4* gh = (const uint4*)g_imgW_h[mat];
            const uint4* gl = (const uint4*)g_imgW_l[mat];
            for (int idx = tid; idx < 128 * 16; idx += 256) {
                int row = idx >> 4, q = idx & 15;
                ((uint4*)(BH + row * KN_SA))[q] = gh[row * 16 + q];
                ((uint4*)(BL + row * KN_SA))[q] = gl[row * 16 + q];
            }
        }
        __syncthreads();

        float d[2][8][4];
#pragma unroll
        for (int mi = 0; mi < 2; ++mi)
#pragma unroll
            for (int ni = 0; ni < 8; ++ni)
#pragma unroll
                for (int c = 0; c < 4; ++c) d[mi][ni][c] = 0.f;

#pragma unroll 2
        for (int ks = 0; ks < 8; ++ks) {
            const int k0 = ks * 16;
            uint32_t ah[2][4];
#pragma unroll
            for (int mi = 0; mi < 2; ++mi) {
                int row = wm * 32 + mi * 16 + lrow;
                ldsm4(ah[mi], sb + (uint32_t)(row * (KN_SA * 4)) + (uint32_t)((k0 + lk) * 2));
            }
#pragma unroll
            for (int g = 0; g < 4; ++g) {
                int n = wn * 64 + g * 16 + lrow;
                uint32_t bo = (uint32_t)(n * (KN_SA * 4)) + (uint32_t)((k0 + lk) * 2);
                uint32_t bh[4], bl[4];
                ldsm4(bh, sb + 8704u * 4u + bo);
                ldsm4(bl, sb + 17408u * 4u + bo);
#pragma unroll
                for (int mi = 0; mi < 2; ++mi) {
                    mma16816(d[mi][2 * g + 0], ah[mi], bh[0], bh[2]);
                    mma16816(d[mi][2 * g + 1], ah[mi], bh[1], bh[3]);
                    mma16816(d[mi][2 * g + 0], ah[mi], bl[0], bl[2]);
                    mma16816(d[mi][2 * g + 1], ah[mi], bl[1], bl[3]);
                }
            }
        }

        const float* bias = (mat == 0) ? bq : (mat == 1) ? bk : (mat == 2) ? bv : bs;
        uint32_t* dsth    = (mat == 0) ? g_qh : (mat == 1) ? g_kh : g_vh;

#pragma unroll
        for (int g = 0; g < 4; ++g) {
            const int mi = g >> 1;
            const int c0 = (g & 1) * 2;
            int r = wm * 32 + mi * 16 + (g & 1) * 8 + lr;
            int node = base + r;
            if (node < N_NODES) {
                const float4* b4 = (const float4*)(bias + wn * 64 + l2 * 16);
                float o[16];
#pragma unroll
                for (int q = 0; q < 4; ++q) {
                    float4 bb = b4[q];
                    o[4 * q + 0] = d[mi][2 * q + 0][c0]     + bb.x;
                    o[4 * q + 1] = d[mi][2 * q + 0][c0 + 1] + bb.y;
                    o[4 * q + 2] = d[mi][2 * q + 1][c0]     + bb.z;
                    o[4 * q + 3] = d[mi][2 * q + 1][c0 + 1] + bb.w;
                }
                if (mat < 3) {
                    uint32_t hw[8];
#pragma unroll
                    for (int w = 0; w < 8; ++w)
                        hw[w] = packh2(o[2 * w], o[2 * w + 1]);
                    uint4* dst4 = (uint4*)&dsth[(size_t)node * 64 + wn * 32 + l2 * 8];
                    dst4[0] = make_uint4(hw[0], hw[1], hw[2], hw[3]);
                    dst4[1] = make_uint4(hw[4], hw[5], hw[6], hw[7]);
                } else {
                    float4* dst4 = (float4*)(out + (size_t)node * 128 + wn * 64 + l2 * 16);
#pragma unroll
                    for (int q = 0; q < 4; ++q)
                        dst4[q] = make_float4(o[4 * q], o[4 * q + 1], o[4 * q + 2], o[4 * q + 3]);
                }
            }
        }
        __syncthreads();
    }
}

// ---------------- edge GEMM (K=128) + poly time-enc + attention + scatter ----------------
// SMEM words: src[2][128]@0, dst@256, rel@512, Ctab@768 (640w),
// AH@1408 (128*68), BH@10112 (128*68); total 18816 w = 75264 B
#define KE_SA 68
#define KE_SMEM (18816 * 4)
#define AHB (1408u * 4u)
#define BHB (10112u * 4u)

__device__ __forceinline__ void edge_load_idx(uint32_t* sm4, int buf, int base,
                                              const void* __restrict__ ei,
                                              const float* __restrict__ t,
                                              const float* __restrict__ lu)
{
    int tid = threadIdx.x;
    if (tid < 128) {
        int*   s_src = (int*)(sm4)        + buf * 128;
        int*   s_dst = (int*)(sm4 + 256)  + buf * 128;
        float* s_rel = (float*)(sm4 + 512) + buf * 128;
        int edge = base + tid;
        if (edge < N_EDGES) {
            int s, dd;
            if (g_is64) {
                s  = (int)((const long long*)ei)[edge];
                dd = (int)((const long long*)ei)[N_EDGES + edge];
            } else {
                s  = ((const int*)ei)[edge];
                dd = ((const int*)ei)[N_EDGES + edge];
            }
            s_src[tid] = s;
            s_dst[tid] = dd;
            s_rel[tid] = t[edge] - lu[s];
        } else {
            s_src[tid] = -1; s_dst[tid] = 0; s_rel[tid] = 0.f;
        }
    }
}

__device__ __forceinline__ void edge_build_A(uint32_t* sm4, int base,
                                             const float* __restrict__ msg)
{
    int tid = threadIdx.x;
    uint32_t* AH = sm4 + 1408;
    for (int idx = tid; idx < 128 * 16; idx += 256) {
        int i = idx >> 4, p4 = idx & 15;
        int edge = base + i;
        float v[8] = {0.f, 0.f, 0.f, 0.f, 0.f, 0.f, 0.f, 0.f};
        if (edge < N_EDGES) ldg_ef8(msg + (size_t)edge * 128 + p4 * 8, v);
#pragma unroll
        for (int j = 0; j < 4; ++j)
            AH[i * KE_SA + p4 * 4 + j] = packh2(v[2 * j], v[2 * j + 1]);
    }
}

__global__ void __launch_bounds__(256, 2)
k_edge_tc(const void* __restrict__ ei,
          const float* __restrict__ t,
          const float* __restrict__ last_update,
          const float* __restrict__ msg)
{
    extern __shared__ uint32_t sm4[];
    const uint32_t sb = s2u(sm4);
    const int tid = threadIdx.x;
    const int wid = tid >> 5;
    const int lane = tid & 31;

    // B image + Ctab -> SMEM once
    {
        const uint4* gh = (const uint4*)g_imgWe_h;
        uint32_t* BH = sm4 + 10112;
        for (int idx = tid; idx < 128 * 16; idx += 256) {
            int row = idx >> 4, q = idx & 15;
            ((uint4*)(BH + row * KE_SA))[q] = gh[row * 16 + q];
        }
        float* sC = (float*)(sm4 + 768);
        for (int i = tid; i < 640; i += 256) sC[i] = g_Ctab[i];
    }
    __syncthreads();

    const int wm = wid & 3;
    const int wn = wid >> 2;
    const int lrow = lane & 15;
    const int lk   = (lane >> 4) * 8;
    const int l2   = lane & 3;
    const int lr   = lane >> 2;
    const float* sC = (const float*)(sm4 + 768);
    const int cb = wn * 64 + l2 * 16;   // lane's first logical col

    int tile = blockIdx.x;
    if (tile < NT_EDGE) {
        edge_load_idx(sm4, 0, tile * 128, ei, t, last_update);
        edge_build_A(sm4, tile * 128, msg);
    }
    __syncthreads();

    int buf = 0;
    for (; tile < NT_EDGE; tile += gridDim.x) {
        int nxt = tile + gridDim.x;
        if (nxt < NT_EDGE)
            edge_load_idx(sm4, buf ^ 1, nxt * 128, ei, t, last_update);

        // -------- MMA: fp16 single pass, K=128 --------
        float d[2][8][4];
#pragma unroll
        for (int mi = 0; mi < 2; ++mi)
#pragma unroll
            for (int ni = 0; ni < 8; ++ni)
#pragma unroll
                for (int c = 0; c < 4; ++c) d[mi][ni][c] = 0.f;

#pragma unroll 2
        for (int ks = 0; ks < 8; ++ks) {
            const int k0 = ks * 16;
            uint32_t ah[2][4];
#pragma unroll
            for (int mi = 0; mi < 2; ++mi) {
                int row = wm * 32 + mi * 16 + lrow;
                ldsm4(ah[mi], sb + AHB + (uint32_t)(row * (KE_SA * 4)) + (uint32_t)((k0 + lk) * 2));
            }
#pragma unroll
            for (int g = 0; g < 4; ++g) {
                int n = wn * 64 + g * 16 + lrow;
                uint32_t bh[4];
                ldsm4(bh, sb + BHB + (uint32_t)(n * (KE_SA * 4)) + (uint32_t)((k0 + lk) * 2));
#pragma unroll
                for (int mi = 0; mi < 2; ++mi) {
                    mma16816(d[mi][2 * g + 0], ah[mi], bh[0], bh[2]);
                    mma16816(d[mi][2 * g + 1], ah[mi], bh[1], bh[3]);
                }
            }
        }
        __syncthreads();

        if (nxt < NT_EDGE)
            edge_build_A(sm4, nxt * 128, msg);

        // -------- epilogue: poly time-enc + attention + packed-half atomics --------
        {
            const int* s_src   = (const int*)(sm4)        + buf * 128;
            const int* s_dst   = (const int*)(sm4 + 256)  + buf * 128;
            const float* s_rel = (const float*)(sm4 + 512) + buf * 128;
#pragma unroll
            for (int g = 0; g < 4; ++g) {
                const int mi = g >> 1;
                const int c0 = (g & 1) * 2;
                int r = wm * 32 + mi * 16 + (g & 1) * 8 + lr;
                int sn = s_src[r];
                int dn = s_dst[r];
                float rel = s_rel[r];
                bool valid = (sn >= 0);
                int sn2 = valid ? sn : 0;
                int dn2 = valid ? dn : 0;

                // e = d + Taylor(rel): pe[c] = C0 + rel(C1 + rel(C2 + rel(C3 + rel C4)))
                float pe[16];
#pragma unroll
                for (int q = 0; q < 4; ++q) {
                    float4 a0 = *(const float4*)&sC[0 * 128 + cb + 4 * q];
                    float4 a1 = *(const float4*)&sC[1 * 128 + cb + 4 * q];
                    float4 a2 = *(const float4*)&sC[2 * 128 + cb + 4 * q];
                    float4 a3 = *(const float4*)&sC[3 * 128 + cb + 4 * q];
                    float4 a4 = *(const float4*)&sC[4 * 128 + cb + 4 * q];
                    pe[4 * q + 0] = fmaf(fmaf(fmaf(fmaf(a4.x, rel, a3.x), rel, a2.x), rel, a1.x), rel, a0.x);
                    pe[4 * q + 1] = fmaf(fmaf(fmaf(fmaf(a4.y, rel, a3.y), rel, a2.y), rel, a1.y), rel, a0.y);
                    pe[4 * q + 2] = fmaf(fmaf(fmaf(fmaf(a4.z, rel, a3.z), rel, a2.z), rel, a1.z), rel, a0.z);
                    pe[4 * q + 3] = fmaf(fmaf(fmaf(fmaf(a4.w, rel, a3.w), rel, a2.w), rel, a1.w), rel, a0.w);
                }

                const uint4* qp = (const uint4*)&g_qh[(size_t)dn2 * 64 + wn * 32 + l2 * 8];
                const uint4* kp = (const uint4*)&g_kh[(size_t)sn2 * 64 + wn * 32 + l2 * 8];
                uint4 qa = qp[0], qb = qp[1];
                uint4 ka = kp[0], kb = kp[1];
                uint32_t qw[8] = {qa.x, qa.y, qa.z, qa.w, qb.x, qb.y, qb.z, qb.w};
                uint32_t kw[8] = {ka.x, ka.y, ka.z, ka.w, kb.x, kb.y, kb.z, kb.w};

                float s = 0.f;
#pragma unroll
                for (int w = 0; w < 8; ++w) {
                    float2 q2 = unpackh2(qw[w]);
                    float2 k2 = unpackh2(kw[w]);
                    s += q2.x * (k2.x + d[mi][w][c0]     + pe[2 * w]);
                    s += q2.y * (k2.y + d[mi][w][c0 + 1] + pe[2 * w + 1]);
                }
                s += __shfl_xor_sync(0xffffffffu, s, 1);
                s += __shfl_xor_sync(0xffffffffu, s, 2);
                float alv = __expf(s * 0.125f);

                const uint4* vp = (const uint4*)&g_vh[(size_t)sn2 * 64 + wn * 32 + l2 * 8];
                uint4 va = vp[0], vb = vp[1];
                uint32_t vw[8] = {va.x, va.y, va.z, va.w, vb.x, vb.y, vb.z, vb.w};

                uint32_t ho[8];
#pragma unroll
                for (int w = 0; w < 8; ++w) {
                    float2 v2 = unpackh2(vw[w]);
                    float ox = (v2.x + d[mi][w][c0]     + pe[2 * w])     * alv;
                    float oy = (v2.y + d[mi][w][c0 + 1] + pe[2 * w + 1]) * alv;
                    ho[w] = packh2(ox, oy);
                }
                if (valid) {
                    uint32_t* p = &g_acch[(size_t)dn * 64 + wn * 32 + l2 * 8];
                    asm volatile("red.global.add.noftz.v4.f16x2 [%0], {%1,%2,%3,%4};"
                                 :: "l"(p), "r"(ho[0]), "r"(ho[1]), "r"(ho[2]), "r"(ho[3]) : "memory");
                    asm volatile("red.global.add.noftz.v4.f16x2 [%0], {%1,%2,%3,%4};"
                                 :: "l"(p + 4), "r"(ho[4]), "r"(ho[5]), "r"(ho[6]), "r"(ho[7]) : "memory");
                    if (l2 == 0)
                        asm volatile("red.global.add.f32 [%0], %1;"
                                     :: "l"(&g_asum[dn * 2 + wn]), "f"(alv) : "memory");
                }
            }
        }
        __syncthreads();
        buf ^= 1;
    }
}

// ---------------- final: out = skip + acc / asum ----------------
__global__ void __launch_bounds__(256)
k_final(float* __restrict__ out)
{
    int idx = blockIdx.x * blockDim.x + threadIdx.x;
    if (idx >= N_NODES * 32) return;
    int n  = idx >> 5;
    int c4 = idx & 31;
    int h  = c4 >> 4;
    float inv = 1.f / (g_asum[n * 2 + h] + 1e-16f);
    float2 a0 = unpackh2(g_acch[(size_t)n * 64 + c4 * 2]);
    float2 a1 = unpackh2(g_acch[(size_t)n * 64 + c4 * 2 + 1]);
    float4 o = ((float4*)out)[idx];
    o.x += a0.x * inv; o.y += a0.y * inv; o.z += a1.x * inv; o.w += a1.y * inv;
    ((float4*)out)[idx] = o;
}

// ---------------- launch ----------------
extern "C" void kernel_launch(void* const* d_in, const int* in_sizes, int n_in,
                              void* d_out, int out_size)
{
    const float* x    = (const float*)d_in[0];
    const float* lu   = (const float*)d_in[1];
    const float* t    = (const float*)d_in[2];
    const float* msg  = (const float*)d_in[3];
    const float* tw   = (const float*)d_in[4];
    const float* tb   = (const float*)d_in[5];
    const float* Wq   = (const float*)d_in[6];
    const float* bq   = (const float*)d_in[7];
    const float* Wk   = (const float*)d_in[8];
    const float* bk   = (const float*)d_in[9];
    const float* Wv   = (const float*)d_in[10];
    const float* bv   = (const float*)d_in[11];
    const float* We   = (const float*)d_in[12];
    const float* Wsk  = (const float*)d_in[13];
    const float* bsk  = (const float*)d_in[14];
    const void*  ei   = d_in[15];
    float* out = (float*)d_out;

    cudaFuncSetAttribute(k_node_tc, cudaFuncAttributeMaxDynamicSharedMemorySize, KN_SMEM);
    cudaFuncSetAttribute(k_edge_tc, cudaFuncAttributeMaxDynamicSharedMemorySize, KE_SMEM);

    k_detect<<<1, 256>>>((const int*)ei);                              // my 0
    k_fused<<<FB_TOTAL, 256>>>(We, Wq, Wk, Wv, Wsk, tw, tb);           // my 1
    k_node_tc<<<NT_NODE, 256, KN_SMEM>>>(x, bq, bk, bv, bsk, out);     // my 2
    k_edge_tc<<<304, 256, KE_SMEM>>>(ei, t, lu, msg);                  // my 3 (global 5)
    k_final<<<(N_NODES * 32 + 255) / 256, 256>>>(out);                 // my 4
}

// round 16
// speedup vs baseline: 1.4274x; 1.4274x over previous
#include <cuda_runtime.h>
#include <cuda_fp16.h>
#include <cstdint>

#define N_NODES 50000
#define N_EDGES 500000
#define NT_EDGE ((N_EDGES + 127) / 128)   // 3907
#define NT_NODE ((N_NODES + 127) / 128)   // 391

#define FB_ZERO  6250
#define FB_PREP  176
#define FB_TOTAL (FB_ZERO + FB_PREP)

// ---------------- global scratch ----------------
__device__ uint32_t g_qh[(size_t)N_NODES * 64];
__device__ uint32_t g_kh[(size_t)N_NODES * 64];
__device__ uint32_t g_vh[(size_t)N_NODES * 64];
__device__ uint32_t g_acch[(size_t)N_NODES * 64];   // fp16x2 accumulator
__device__ float g_asum[(size_t)N_NODES * 2];
__device__ int   g_is64;
// weight images with PERMUTED N order (fragment-contiguous)
__device__ uint32_t g_imgWe_h[128 * 96];
__device__ uint32_t g_imgW_h[4][128 * 64], g_imgW_l[4][128 * 64];

// fragment->contiguous column permutation (within each 64-col block)
__device__ __forceinline__ int permN(int n) {
    int p = n & 63;
    return (n & 64) + (((p & 7) >> 1) << 4) + ((p >> 3) << 1) + (p & 1);
}

// ---------------- helpers ----------------
__device__ __forceinline__ uint32_t s2u(const void* p) {
    uint32_t r;
    asm("{ .reg .u64 t; cvta.to.shared.u64 t, %1; cvt.u32.u64 %0, t; }" : "=r"(r) : "l"(p));
    return r;
}

__device__ __forceinline__ void ldsm4(uint32_t* r, uint32_t addr) {
    asm volatile("ldmatrix.sync.aligned.m8n8.x4.shared.b16 {%0,%1,%2,%3}, [%4];"
                 : "=r"(r[0]), "=r"(r[1]), "=r"(r[2]), "=r"(r[3]) : "r"(addr));
}

__device__ __forceinline__ void mma16816(float* d, const uint32_t* a, uint32_t b0, uint32_t b1) {
    asm volatile("mma.sync.aligned.m16n8k16.row.col.f32.f16.f16.f32 "
                 "{%0,%1,%2,%3}, {%4,%5,%6,%7}, {%8,%9}, {%0,%1,%2,%3};"
                 : "+f"(d[0]), "+f"(d[1]), "+f"(d[2]), "+f"(d[3])
                 : "r"(a[0]), "r"(a[1]), "r"(a[2]), "r"(a[3]), "r"(b0), "r"(b1));
}

__device__ __forceinline__ uint32_t packh2(float a, float b) {
    __half2 h = __floats2half2_rn(a, b);
    return *reinterpret_cast<uint32_t*>(&h);
}

__device__ __forceinline__ float2 unpackh2(uint32_t u) {
    return __half22float2(*reinterpret_cast<__half2*>(&u));
}

__device__ __forceinline__ void splith(float a, float b, uint32_t& hi, uint32_t& lo) {
    __half2 h = __floats2half2_rn(a, b);
    float ra = a - __low2float(h);
    float rb = b - __high2float(h);
    __half2 l = __floats2half2_rn(ra, rb);
    hi = *reinterpret_cast<uint32_t*>(&h);
    lo = *reinterpret_cast<uint32_t*>(&l);
}

__device__ __forceinline__ void ldg_ef8(const float* p, float* v) {
    uint32_t r0, r1, r2, r3, r4, r5, r6, r7;
    asm("ld.global.L2::evict_first.v8.b32 {%0,%1,%2,%3,%4,%5,%6,%7}, [%8];"
        : "=r"(r0), "=r"(r1), "=r"(r2), "=r"(r3),
          "=r"(r4), "=r"(r5), "=r"(r6), "=r"(r7) : "l"(p));
    v[0] = __uint_as_float(r0); v[1] = __uint_as_float(r1);
    v[2] = __uint_as_float(r2); v[3] = __uint_as_float(r3);
    v[4] = __uint_as_float(r4); v[5] = __uint_as_float(r5);
    v[6] = __uint_as_float(r6); v[7] = __uint_as_float(r7);
}

// ---------------- detect ----------------
__global__ void k_detect(const int* __restrict__ words)
{
    __shared__ int nz;
    if (threadIdx.x == 0) nz = 0;
    __syncthreads();
    int local = 0;
    for (int idx = threadIdx.x; idx < 4096; idx += blockDim.x)
        if (words[2 * idx + 1] != 0) local = 1;
    if (local) atomicOr(&nz, 1);
    __syncthreads();
    if (threadIdx.x == 0) g_is64 = (nz == 0) ? 1 : 0;
}

// ---------------- fused zero + prep (permuted N) ----------------
__global__ void k_fused(const float* __restrict__ We,
                        const float* __restrict__ Wq, const float* __restrict__ Wk,
                        const float* __restrict__ Wv, const float* __restrict__ Ws)
{
    int b = blockIdx.x;
    if (b < FB_ZERO) {
        int i = b * 256 + threadIdx.x;
        if (i < N_NODES * 2) g_asum[i] = 0.f;
        if (i < N_NODES * 16) ((uint4*)g_acch)[i] = make_uint4(0u, 0u, 0u, 0u);
        return;
    }
    b -= FB_ZERO;
    {
        int idx = b * 256 + threadIdx.x;
        if (idx < 12288) {
            int n = idx / 96, p = idx % 96;
            int ns = permN(n);
            float a = We[(2 * p) * 128 + ns];
            float bb = We[(2 * p + 1) * 128 + ns];
            g_imgWe_h[idx] = packh2(a, bb);
        } else if (idx < 45056) {
            int r = idx - 12288;
            int mat = r >> 13;
            int w_  = r & 8191;
            int n = w_ >> 6, p = w_ & 63;
            int ns = permN(n);
            const float* W = (mat == 0) ? Wq : (mat == 1) ? Wk : (mat == 2) ? Wv : Ws;
            float a = W[(2 * p) * 128 + ns];
            float bb = W[(2 * p + 1) * 128 + ns];
            uint32_t h, l; splith(a, bb, h, l);
            g_imgW_h[mat][w_] = h; g_imgW_l[mat][w_] = l;
        }
    }
}

// ---------------- node GEMM: fp16 2-pass (B compensated), all 4 matrices ----------------
#define KN_SA 68
#define KN_SMEM (26112 * 4)

__global__ void __launch_bounds__(256, 2)
k_node_tc(const float* __restrict__ x,
          const float* __restrict__ bq, const float* __restrict__ bk,
          const float* __restrict__ bv, const float* __restrict__ bs,
          float* __restrict__ out)
{
    extern __shared__ uint32_t sm4[];
    const uint32_t sb = s2u(sm4);
    const int tid = threadIdx.x;
    const int wid = tid >> 5;
    const int lane = tid & 31;
    const int base = blockIdx.x * 128;

    uint32_t* AH = sm4;
    uint32_t* BH = sm4 + 8704;
    uint32_t* BL = sm4 + 17408;

    for (int idx = tid; idx < 128 * 16; idx += 256) {
        int i = idx >> 4, p4 = idx & 15;
        int node = base + i;
        float v[8] = {0.f, 0.f, 0.f, 0.f, 0.f, 0.f, 0.f, 0.f};
        if (node < N_NODES) ldg_ef8(x + (size_t)node * 128 + p4 * 8, v);
#pragma unroll
        for (int j = 0; j < 4; ++j)
            AH[i * KN_SA + p4 * 4 + j] = packh2(v[2 * j], v[2 * j + 1]);
    }

    const int wm = wid & 3;
    const int wn = wid >> 2;
    const int lrow = lane & 15;
    const int lk   = (lane >> 4) * 8;
    const int l2   = lane & 3;
    const int lr   = lane >> 2;

    for (int mat = 0; mat < 4; ++mat) {
        {
            const uint4* gh = (const uint4*)g_imgW_h[mat];
            const uint4* gl = (const uint4*)g_imgW_l[mat];
            for (int idx = tid; idx < 128 * 16; idx += 256) {
                int row = idx >> 4, q = idx & 15;
                ((uint4*)(BH + row * KN_SA))[q] = gh[row * 16 + q];
                ((uint4*)(BL + row * KN_SA))[q] = gl[row * 16 + q];
            }
        }
        __syncthreads();

        float d[2][8][4];
#pragma unroll
        for (int mi = 0; mi < 2; ++mi)
#pragma unroll
            for (int ni = 0; ni < 8; ++ni)
#pragma unroll
                for (int c = 0; c < 4; ++c) d[mi][ni][c] = 0.f;

#pragma unroll 2
        for (int ks = 0; ks < 8; ++ks) {
            const int k0 = ks * 16;
            uint32_t ah[2][4];
#pragma unroll
            for (int mi = 0; mi < 2; ++mi) {
                int row = wm * 32 + mi * 16 + lrow;
                ldsm4(ah[mi], sb + (uint32_t)(row * (KN_SA * 4)) + (uint32_t)((k0 + lk) * 2));
            }
#pragma unroll
            for (int g = 0; g < 4; ++g) {
                int n = wn * 64 + g * 16 + lrow;
                uint32_t bo = (uint32_t)(n * (KN_SA * 4)) + (uint32_t)((k0 + lk) * 2);
                uint32_t bh[4], bl[4];
                ldsm4(bh, sb + 8704u * 4u + bo);
                ldsm4(bl, sb + 17408u * 4u + bo);
#pragma unroll
                for (int mi = 0; mi < 2; ++mi) {
                    mma16816(d[mi][2 * g + 0], ah[mi], bh[0], bh[2]);
                    mma16816(d[mi][2 * g + 1], ah[mi], bh[1], bh[3]);
                    mma16816(d[mi][2 * g + 0], ah[mi], bl[0], bl[2]);
                    mma16816(d[mi][2 * g + 1], ah[mi], bl[1], bl[3]);
                }
            }
        }

        const float* bias = (mat == 0) ? bq : (mat == 1) ? bk : (mat == 2) ? bv : bs;
        uint32_t* dsth    = (mat == 0) ? g_qh : (mat == 1) ? g_kh : g_vh;

#pragma unroll
        for (int g = 0; g < 4; ++g) {
            const int mi = g >> 1;
            const int c0 = (g & 1) * 2;
            int r = wm * 32 + mi * 16 + (g & 1) * 8 + lr;
            int node = base + r;
            if (node < N_NODES) {
                const float4* b4 = (const float4*)(bias + wn * 64 + l2 * 16);
                float o[16];
#pragma unroll
                for (int q = 0; q < 4; ++q) {
                    float4 bb = b4[q];
                    o[4 * q + 0] = d[mi][2 * q + 0][c0]     + bb.x;
                    o[4 * q + 1] = d[mi][2 * q + 0][c0 + 1] + bb.y;
                    o[4 * q + 2] = d[mi][2 * q + 1][c0]     + bb.z;
                    o[4 * q + 3] = d[mi][2 * q + 1][c0 + 1] + bb.w;
                }
                if (mat < 3) {
                    uint32_t hw[8];
#pragma unroll
                    for (int w = 0; w < 8; ++w)
                        hw[w] = packh2(o[2 * w], o[2 * w + 1]);
                    uint4* dst4 = (uint4*)&dsth[(size_t)node * 64 + wn * 32 + l2 * 8];
                    dst4[0] = make_uint4(hw[0], hw[1], hw[2], hw[3]);
                    dst4[1] = make_uint4(hw[4], hw[5], hw[6], hw[7]);
                } else {
                    float4* dst4 = (float4*)(out + (size_t)node * 128 + wn * 64 + l2 * 16);
#pragma unroll
                    for (int q = 0; q < 4; ++q)
                        dst4[q] = make_float4(o[4 * q], o[4 * q + 1], o[4 * q + 2], o[4 * q + 3]);
                }
            }
        }
        __syncthreads();
    }
}

// ---------------- edge GEMM + attention + scatter (persistent, 128-tile, 2 CTA/SM) ----------------
#define KE_SA 100
#define KE_SMEM (26496 * 4)
#define AHB (896u * 4u)
#define BHB (13696u * 4u)

__device__ __forceinline__ void edge_load_idx(uint32_t* sm4, int buf, int base,
                                              const void* __restrict__ ei,
                                              const float* __restrict__ t,
                                              const float* __restrict__ lu)
{
    int tid = threadIdx.x;
    if (tid < 128) {
        int*   s_src = (int*)(sm4)        + buf * 128;
        int*   s_dst = (int*)(sm4 + 256)  + buf * 128;
        float* s_rel = (float*)(sm4 + 512) + buf * 128;
        int edge = base + tid;
        if (edge < N_EDGES) {
            int s, dd;
            if (g_is64) {
                s  = (int)((const long long*)ei)[edge];
                dd = (int)((const long long*)ei)[N_EDGES + edge];
            } else {
                s  = ((const int*)ei)[edge];
                dd = ((const int*)ei)[N_EDGES + edge];
            }
            s_src[tid] = s;
            s_dst[tid] = dd;
            s_rel[tid] = t[edge] - lu[s];
        } else {
            s_src[tid] = -1; s_dst[tid] = 0; s_rel[tid] = 0.f;
        }
    }
}

__device__ __forceinline__ void edge_build_A(uint32_t* sm4, int buf, int base,
                                             const float* __restrict__ msg)
{
    int tid = threadIdx.x;
    float* s_rel = (float*)(sm4 + 512) + buf * 128;
    float* s_tw  = (float*)(sm4 + 768);
    float* s_tb  = (float*)(sm4 + 832);
    uint32_t* AH = sm4 + 896;
    for (int idx = tid; idx < 128 * 32; idx += 256) {
        int i = idx >> 5, p = idx & 31;
        float rel = s_rel[i];
        float c0 = __cosf(fmaf(rel, s_tw[2 * p],     s_tb[2 * p]));
        float c1 = __cosf(fmaf(rel, s_tw[2 * p + 1], s_tb[2 * p + 1]));
        AH[i * KE_SA + p] = packh2(c0, c1);
    }
    for (int idx = tid; idx < 128 * 16; idx += 256) {
        int i = idx >> 4, p4 = idx & 15;
        int edge = base + i;
        float v[8] = {0.f, 0.f, 0.f, 0.f, 0.f, 0.f, 0.f, 0.f};
        if (edge < N_EDGES) ldg_ef8(msg + (size_t)edge * 128 + p4 * 8, v);
#pragma unroll
        for (int j = 0; j < 4; ++j)
            AH[i * KE_SA + 32 + p4 * 4 + j] = packh2(v[2 * j], v[2 * j + 1]);
    }
}

__global__ void __launch_bounds__(256, 2)
k_edge_tc(const void* __restrict__ ei,
          const float* __restrict__ t,
          const float* __restrict__ last_update,
          const float* __restrict__ msg,
          const float* __restrict__ time_w,
          const float* __restrict__ time_b)
{
    extern __shared__ uint32_t sm4[];
    const uint32_t sb = s2u(sm4);
    const int tid = threadIdx.x;
    const int wid = tid >> 5;
    const int lane = tid & 31;

    {
        const uint4* gh = (const uint4*)g_imgWe_h;
        uint32_t* BH = sm4 + 13696;
        for (int idx = tid; idx < 128 * 24; idx += 256) {
            int row = idx / 24, q = idx % 24;
            ((uint4*)(BH + row * KE_SA))[q] = gh[row * 24 + q];
        }
    }
    if (tid < 64) {
        ((float*)(sm4 + 768))[tid] = time_w[tid];
        ((float*)(sm4 + 832))[tid] = time_b[tid];
    }
    __syncthreads();

    const int wm = wid & 3;
    const int wn = wid >> 2;
    const int lrow = lane & 15;
    const int lk   = (lane >> 4) * 8;
    const int l2   = lane & 3;
    const int lr   = lane >> 2;

    int tile = blockIdx.x;
    if (tile < NT_EDGE) {
        edge_load_idx(sm4, 0, tile * 128, ei, t, last_update);
        __syncthreads();
        edge_build_A(sm4, 0, tile * 128, msg);
    }
    __syncthreads();

    int buf = 0;
    for (; tile < NT_EDGE; tile += gridDim.x) {
        int nxt = tile + gridDim.x;
        if (nxt < NT_EDGE)
            edge_load_idx(sm4, buf ^ 1, nxt * 128, ei, t, last_update);

        // -------- MMA: fp16 single pass, K=192 --------
        float d[2][8][4];
#pragma unroll
        for (int mi = 0; mi < 2; ++mi)
#pragma unroll
            for (int ni = 0; ni < 8; ++ni)
#pragma unroll
                for (int c = 0; c < 4; ++c) d[mi][ni][c] = 0.f;

#pragma unroll 3
        for (int ks = 0; ks < 12; ++ks) {
            const int k0 = ks * 16;
            uint32_t ah[2][4];
#pragma unroll
            for (int mi = 0; mi < 2; ++mi) {
                int row = wm * 32 + mi * 16 + lrow;
                ldsm4(ah[mi], sb + AHB + (uint32_t)(row * (KE_SA * 4)) + (uint32_t)((k0 + lk) * 2));
            }
#pragma unroll
            for (int g = 0; g < 4; ++g) {
                int n = wn * 64 + g * 16 + lrow;
                uint32_t bh[4];
                ldsm4(bh, sb + BHB + (uint32_t)(n * (KE_SA * 4)) + (uint32_t)((k0 + lk) * 2));
#pragma unroll
                for (int mi = 0; mi < 2; ++mi) {
                    mma16816(d[mi][2 * g + 0], ah[mi], bh[0], bh[2]);
                    mma16816(d[mi][2 * g + 1], ah[mi], bh[1], bh[3]);
                }
            }
        }
        __syncthreads();

        if (nxt < NT_EDGE)
            edge_build_A(sm4, buf ^ 1, nxt * 128, msg);

        // -------- epilogue: coalesced gathers, packed-half v4 atomics --------
        {
            const int* s_src = (const int*)(sm4)       + buf * 128;
            const int* s_dst = (const int*)(sm4 + 256) + buf * 128;
#pragma unroll
            for (int g = 0; g < 4; ++g) {
                const int mi = g >> 1;
                const int c0 = (g & 1) * 2;
                int r = wm * 32 + mi * 16 + (g & 1) * 8 + lr;
                int sn = s_src[r];
                int dn = s_dst[r];
                bool valid = (sn >= 0);
                int sn2 = valid ? sn : 0;
                int dn2 = valid ? dn : 0;

                const uint4* qp = (const uint4*)&g_qh[(size_t)dn2 * 64 + wn * 32 + l2 * 8];
                const uint4* kp = (const uint4*)&g_kh[(size_t)sn2 * 64 + wn * 32 + l2 * 8];
                uint4 qa = qp[0], qb = qp[1];
                uint4 ka = kp[0], kb = kp[1];
                uint32_t qw[8] = {qa.x, qa.y, qa.z, qa.w, qb.x, qb.y, qb.z, qb.w};
                uint32_t kw[8] = {ka.x, ka.y, ka.z, ka.w, kb.x, kb.y, kb.z, kb.w};

                float s = 0.f;
#pragma unroll
                for (int w = 0; w < 8; ++w) {
                    float2 q2 = unpackh2(qw[w]);
                    float2 k2 = unpackh2(kw[w]);
                    s += q2.x * (k2.x + d[mi][w][c0]);
                    s += q2.y * (k2.y + d[mi][w][c0 + 1]);
                }
                s += __shfl_xor_sync(0xffffffffu, s, 1);
                s += __shfl_xor_sync(0xffffffffu, s, 2);
                float alv = __expf(s * 0.125f);

                const uint4* vp = (const uint4*)&g_vh[(size_t)sn2 * 64 + wn * 32 + l2 * 8];
                uint4 va = vp[0], vb = vp[1];
                uint32_t vw[8] = {va.x, va.y, va.z, va.w, vb.x, vb.y, vb.z, vb.w};

                uint32_t ho[8];
#pragma unroll
                for (int w = 0; w < 8; ++w) {
                    float2 v2 = unpackh2(vw[w]);
                    float ox = (v2.x + d[mi][w][c0])     * alv;
                    float oy = (v2.y + d[mi][w][c0 + 1]) * alv;
                    ho[w] = packh2(ox, oy);
                }
                if (valid) {
                    uint32_t* p = &g_acch[(size_t)dn * 64 + wn * 32 + l2 * 8];
                    asm volatile("red.global.add.noftz.v4.f16x2 [%0], {%1,%2,%3,%4};"
                                 :: "l"(p), "r"(ho[0]), "r"(ho[1]), "r"(ho[2]), "r"(ho[3]) : "memory");
                    asm volatile("red.global.add.noftz.v4.f16x2 [%0], {%1,%2,%3,%4};"
                                 :: "l"(p + 4), "r"(ho[4]), "r"(ho[5]), "r"(ho[6]), "r"(ho[7]) : "memory");
                    if (l2 == 0)
                        asm volatile("red.global.add.f32 [%0], %1;"
                                     :: "l"(&g_asum[dn * 2 + wn]), "f"(alv) : "memory");
                }
            }
        }
        __syncthreads();
        buf ^= 1;
    }
}

// ---------------- final: out = skip + acc / asum ----------------
__global__ void __launch_bounds__(256)
k_final(float* __restrict__ out)
{
    int idx = blockIdx.x * blockDim.x + threadIdx.x;
    if (idx >= N_NODES * 32) return;
    int n  = idx >> 5;
    int c4 = idx & 31;
    int h  = c4 >> 4;
    float inv = 1.f / (g_asum[n * 2 + h] + 1e-16f);
    float2 a0 = unpackh2(g_acch[(size_t)n * 64 + c4 * 2]);
    float2 a1 = unpackh2(g_acch[(size_t)n * 64 + c4 * 2 + 1]);
    float4 o = ((float4*)out)[idx];
    o.x += a0.x * inv; o.y += a0.y * inv; o.z += a1.x * inv; o.w += a1.y * inv;
    ((float4*)out)[idx] = o;
}

// ---------------- launch ----------------
extern "C" void kernel_launch(void* const* d_in, const int* in_sizes, int n_in,
                              void* d_out, int out_size)
{
    const float* x    = (const float*)d_in[0];
    const float* lu   = (const float*)d_in[1];
    const float* t    = (const float*)d_in[2];
    const float* msg  = (const float*)d_in[3];
    const float* tw   = (const float*)d_in[4];
    const float* tb   = (const float*)d_in[5];
    const float* Wq   = (const float*)d_in[6];
    const float* bq   = (const float*)d_in[7];
    const float* Wk   = (const float*)d_in[8];
    const float* bk   = (const float*)d_in[9];
    const float* Wv   = (const float*)d_in[10];
    const float* bv   = (const float*)d_in[11];
    const float* We   = (const float*)d_in[12];
    const float* Wsk  = (const float*)d_in[13];
    const float* bsk  = (const float*)d_in[14];
    const void*  ei   = d_in[15];
    float* out = (float*)d_out;

    cudaFuncSetAttribute(k_node_tc, cudaFuncAttributeMaxDynamicSharedMemorySize, KN_SMEM);
    cudaFuncSetAttribute(k_edge_tc, cudaFuncAttributeMaxDynamicSharedMemorySize, KE_SMEM);

    k_detect<<<1, 256>>>((const int*)ei);                              // my 0
    k_fused<<<FB_TOTAL, 256>>>(We, Wq, Wk, Wv, Wsk);                   // my 1
    k_node_tc<<<NT_NODE, 256, KN_SMEM>>>(x, bq, bk, bv, bsk, out);     // my 2
    k_edge_tc<<<304, 256, KE_SMEM>>>(ei, t, lu, msg, tw, tb);          // my 3 (global 5)
    k_final<<<(N_NODES * 32 + 255) / 256, 256>>>(out);                 // my 4
}